// round 4
// baseline (speedup 1.0000x reference)
#include <cuda_runtime.h>
#include <stdint.h>

// Problem constants (fixed by the reference).
#define MM      512      // checks
#define NN      1024     // variables
#define EE      3072     // edges
#define NITERS  10
#define THREADS 512
#define WB      2                 // batch lanes per thread (float2)
#define CSTRIDE 7                 // float2 slots per check (56B stride -> conflict-free)
#define CSLOTS  (MM * CSTRIDE)    // 3584 float2
#define LW_SLOTS 1152             // llr table with v + (v>>4) expansion (max 1086)

#define LOG2E 1.4426950408889634f
#define LN2   0.6931471805599453f
#define CLIP  0.999995f
#define UCLAMP 24.0f              // upper clamp on log2-domain sum (overflow guard)

// ---------------- device-global scratch (no runtime allocation) --------------
// Per-iteration packed edge meta: {i0_slot | i1_slot<<16, w0, w1, lw*log2e}
__device__ __align__(16) uint4 g_meta[NITERS * EE];       // 480 KB
__device__ unsigned g_vslotp[EE / 2];                     // packed u16 llr-slot pairs
__device__ uint2  g_finidx[MM];                           // padded final edge slots
__device__ float4 g_finw[MM];                             // {wf0*ln2, wf1*ln2, wf2*ln2, llr_final}

__device__ __forceinline__ int slot7(int e) { return (e / 6) * CSTRIDE + (e % 6); }
__device__ __forceinline__ int lwslot(int v) { return v + (v >> 4); }

// ---------------------------------- prep -------------------------------------
__global__ void prep_kernel(const float* __restrict__ w_iter,
                            const float* __restrict__ llr_iter,
                            const float* __restrict__ w_final,
                            const float* __restrict__ llr_final,
                            const int*   __restrict__ v_sum,
                            const int*   __restrict__ edge_var,
                            const int*   __restrict__ fin_idx) {
    int t = blockIdx.x * blockDim.x + threadIdx.x;
    if (t < NITERS * EE) {
        int e = t % EE;
        uint4 p;
        p.x = (unsigned)slot7(v_sum[2 * e]) | ((unsigned)slot7(v_sum[2 * e + 1]) << 16);
        p.y = __float_as_uint(w_iter[2 * t]);                       // w_iter[it][2e]
        p.z = __float_as_uint(w_iter[2 * t + 1]);                   // w_iter[it][2e+1]
        p.w = __float_as_uint(llr_iter[(t / EE) * NN + edge_var[e]] * LOG2E);
        g_meta[t] = p;
    }
    if (t < EE / 2)
        g_vslotp[t] = (unsigned)lwslot(edge_var[2 * t]) |
                      ((unsigned)lwslot(edge_var[2 * t + 1]) << 16);
    if (t < MM) {
        g_finidx[t] = make_uint2((unsigned)slot7(fin_idx[3 * t]) |
                                 ((unsigned)slot7(fin_idx[3 * t + 1]) << 16),
                                 (unsigned)slot7(fin_idx[3 * t + 2]));
        g_finw[t] = make_float4(w_final[3 * t] * LN2, w_final[3 * t + 1] * LN2,
                                w_final[3 * t + 2] * LN2, llr_final[t]);
    }
}

// ------------------------------- fast math -----------------------------------
__device__ __forceinline__ float ex2f_(float x) { float y; asm("ex2.approx.f32 %0, %1;" : "=f"(y) : "f"(x)); return y; }
__device__ __forceinline__ float lg2f_(float x) { float y; asm("lg2.approx.f32 %0, %1;" : "=f"(y) : "f"(x)); return y; }
__device__ __forceinline__ float rcpf_(float x) { float y; asm("rcp.approx.f32 %0, %1;" : "=f"(y) : "f"(x)); return y; }

__device__ __forceinline__ float2 f2mul(float2 a, float2 b) { return make_float2(a.x * b.x, a.y * b.y); }
__device__ __forceinline__ float2 f2add1(float2 a) { return make_float2(a.x + 1.f, a.y + 1.f); }
__device__ __forceinline__ float2 f2sub1(float2 a) { return make_float2(a.x - 1.f, a.y - 1.f); }
// msg = lg2(B + c*A) - lg2(B - c*A)   (log2-domain c2v; ln2 folded into weights)
__device__ __forceinline__ float2 lgpair(float2 B, float2 A) {
    float2 o;
    o.x = lg2f_(fmaf(CLIP, A.x, B.x)) - lg2f_(fmaf(-CLIP, A.x, B.x));
    o.y = lg2f_(fmaf(CLIP, A.y, B.y)) - lg2f_(fmaf(-CLIP, A.y, B.y));
    return o;
}

// --------------------------------- main --------------------------------------
extern __shared__ float2 s_dyn2[];

__global__ void __launch_bounds__(THREADS, 3)
bp_kernel(const float* __restrict__ llr, float* __restrict__ out) {
    float2* s_c2v = s_dyn2;                 // CSLOTS float2 (28 KB), stride-7 padded
    float2* s_llr = s_dyn2 + CSLOTS;        // LW_SLOTS float2 (9 KB)
    const int tid = threadIdx.x;
    const long b0 = (long)blockIdx.x * WB;
    const float* llr0 = llr + b0 * NN;

    // stage raw llr (2 batch lanes per variable) - once
#pragma unroll
    for (int k = 0; k < NN / THREADS; k++) {
        int v = tid + k * THREADS;
        s_llr[lwslot(v)] = make_float2(llr0[v], llr0[NN + v]);
    }
    // zero c2v (iteration 0 reads zeros)
#pragma unroll
    for (int k = 0; k < CSLOTS / THREADS; k++)
        s_c2v[tid + k * THREADS] = make_float2(0.f, 0.f);

    // packed llr-table slots for this thread's 6 edges (iteration-invariant)
    unsigned vp0 = g_vslotp[tid * 3];
    unsigned vp1 = g_vslotp[tid * 3 + 1];
    unsigned vp2 = g_vslotp[tid * 3 + 2];
    __syncthreads();

    float2* dst = s_c2v + tid * CSTRIDE;

    for (int it = 0; it < NITERS; it++) {
        const uint4* meta = g_meta + it * EE + tid * 6;
        float2 E0, E1, E2, E3, E4, E5;
        {
            unsigned vs[6] = { vp0 & 0xFFFFu, vp0 >> 16, vp1 & 0xFFFFu,
                               vp1 >> 16, vp2 & 0xFFFFu, vp2 >> 16 };
            float2 Ev[6];
#pragma unroll
            for (int j = 0; j < 6; j++) {
                uint4 m = meta[j];
                float2 A  = s_c2v[m.x & 0xFFFFu];
                float2 Bv = s_c2v[m.x >> 16];
                float2 L  = s_llr[vs[j]];
                float W0 = __uint_as_float(m.y);
                float W1 = __uint_as_float(m.z);
                float LW = __uint_as_float(m.w);
                float ux = fminf(UCLAMP, fmaf(A.x, W0, fmaf(Bv.x, W1, L.x * LW)));
                float uy = fminf(UCLAMP, fmaf(A.y, W0, fmaf(Bv.y, W1, L.y * LW)));
                Ev[j].x = ex2f_(ux);
                Ev[j].y = ex2f_(uy);
            }
            E0 = Ev[0]; E1 = Ev[1]; E2 = Ev[2]; E3 = Ev[3]; E4 = Ev[4]; E5 = Ev[5];
        }
        __syncthreads();   // all reads of old c2v complete

        // check node: half-split extrinsic products of (E+1) and (E-1)
        {
            float2 ep3 = f2add1(E3), em3 = f2sub1(E3);
            float2 ep4 = f2add1(E4), em4 = f2sub1(E4);
            float2 ep5 = f2add1(E5), em5 = f2sub1(E5);
            float2 p34 = f2mul(ep3, ep4), m34 = f2mul(em3, em4);
            float2 H2p = f2mul(p34, ep5), H2m = f2mul(m34, em5);

            float2 ep0 = f2add1(E0), em0 = f2sub1(E0);
            float2 ep1 = f2add1(E1), em1 = f2sub1(E1);
            float2 ep2 = f2add1(E2), em2 = f2sub1(E2);
            float2 p01 = f2mul(ep0, ep1), m01 = f2mul(em0, em1);
            float2 H1p = f2mul(p01, ep2), H1m = f2mul(m01, em2);

            dst[0] = lgpair(f2mul(f2mul(ep1, ep2), H2p), f2mul(f2mul(em1, em2), H2m));
            dst[1] = lgpair(f2mul(f2mul(ep0, ep2), H2p), f2mul(f2mul(em0, em2), H2m));
            dst[2] = lgpair(f2mul(p01, H2p), f2mul(m01, H2m));
            dst[3] = lgpair(f2mul(f2mul(ep4, ep5), H1p), f2mul(f2mul(em4, em5), H1m));
            dst[4] = lgpair(f2mul(f2mul(ep3, ep5), H1p), f2mul(f2mul(em3, em5), H1m));
            dst[5] = lgpair(f2mul(p34, H1p), f2mul(m34, H1m));
        }
        __syncthreads();   // stores visible before next iteration's gathers
    }

    // final marginalization for variable v = tid (outputs are vars 0..511)
    uint2 fi = g_finidx[tid];
    float4 fw = g_finw[tid];
    float2 A  = s_c2v[fi.x & 0xFFFFu];
    float2 Bv = s_c2v[fi.x >> 16];
    float2 C  = s_c2v[fi.y];
    float2 L  = s_llr[lwslot(tid)];
    float ox = fmaf(A.x, fw.x, fmaf(Bv.x, fw.y, fmaf(C.x, fw.z, L.x * fw.w)));
    float oy = fmaf(A.y, fw.x, fmaf(Bv.y, fw.y, fmaf(C.y, fw.z, L.y * fw.w)));
    out[(b0 + 0) * MM + tid] = rcpf_(1.0f + ex2f_(-ox * LOG2E));
    out[(b0 + 1) * MM + tid] = rcpf_(1.0f + ex2f_(-oy * LOG2E));
}

// ------------------------------ launch ---------------------------------------
extern "C" void kernel_launch(void* const* d_in, const int* in_sizes, int n_in,
                              void* d_out, int out_size) {
    const float* llr       = (const float*)d_in[0];
    const float* w_iter    = (const float*)d_in[1];
    const float* llr_iter  = (const float*)d_in[2];
    const float* w_final   = (const float*)d_in[3];
    const float* llr_final = (const float*)d_in[4];
    const int*   v_sum     = (const int*)d_in[5];
    // d_in[6] = c_prod_idx: redundant (check r owns edges 6r..6r+5 contiguously)
    const int*   edge_var  = (const int*)d_in[7];
    const int*   fin_idx   = (const int*)d_in[8];

    int B = in_sizes[0] / NN;                 // 8192
    size_t smem = (size_t)(CSLOTS + LW_SLOTS) * sizeof(float2);   // 37 KB

    cudaFuncSetAttribute(bp_kernel, cudaFuncAttributeMaxDynamicSharedMemorySize, (int)smem);

    prep_kernel<<<(NITERS * EE + 255) / 256, 256>>>(w_iter, llr_iter, w_final, llr_final,
                                                    v_sum, edge_var, fin_idx);
    bp_kernel<<<B / WB, THREADS, smem>>>(llr, (float*)d_out);
}

// round 5
// speedup vs baseline: 1.2506x; 1.2506x over previous
#include <cuda_runtime.h>
#include <stdint.h>

// Problem constants (fixed by the reference).
#define MM      512      // checks
#define NN      1024     // variables
#define EE      3072     // edges
#define NITERS  10
#define THREADS 512
#define WB      4                 // batch lanes per thread (float4)
#define CSTRIDE 7                 // float4 slots per check (112B stride -> conflict-free)
#define CSLOTS  (MM * CSTRIDE)    // 3584 float4
#define LW_SLOTS 1152             // llr table with v + (v>>3) expansion (max 1150)

#define LOG2E 1.4426950408889634f
#define LN2   0.6931471805599453f
#define CLIP  0.999995f
#define UCLAMP 24.0f              // upper clamp on log2-domain sum (overflow guard)

// ---------------- device-global scratch (no runtime allocation) --------------
// Iteration-varying weights, TRANSPOSED to per-check coalesced layout:
__device__ __align__(16) float4 g_wA[NITERS * MM];   // {w[e0][0],w[e0][1],w[e1][0],w[e1][1]}
__device__ __align__(16) float4 g_wB[NITERS * MM];   // edges 2,3
__device__ __align__(16) float4 g_wC[NITERS * MM];   // edges 4,5
__device__ __align__(16) float4 g_lwA[NITERS * MM];  // lw(var(e0..e3)) * log2e
__device__ __align__(8)  float2 g_lwB[NITERS * MM];  // lw(var(e4..e5)) * log2e
// Iteration-invariant topology (loaded once into registers):
__device__ __align__(16) uint4 g_idxA[MM];           // packed extrinsic slot pairs, edges 0..3
__device__ __align__(8)  uint2 g_idxB[MM];           // edges 4,5
__device__ __align__(16) uint4 g_vsl[MM];            // packed u16 llr-table slots (6 used)
__device__ uint2  g_finidx[MM];
__device__ float4 g_finw[MM];                        // {wf0*ln2, wf1*ln2, wf2*ln2, llr_final}

__device__ __forceinline__ int slot7(int e) { return (e / 6) * CSTRIDE + (e % 6); }
__device__ __forceinline__ int lwslot(int v) { return v + (v >> 3); }

// ---------------------------------- prep -------------------------------------
__global__ void prep_kernel(const float* __restrict__ w_iter,
                            const float* __restrict__ llr_iter,
                            const float* __restrict__ w_final,
                            const float* __restrict__ llr_final,
                            const int*   __restrict__ v_sum,
                            const int*   __restrict__ edge_var,
                            const int*   __restrict__ fin_idx) {
    int t = blockIdx.x * blockDim.x + threadIdx.x;
    if (t < NITERS * MM) {
        int it = t / MM, r = t % MM;
        const float* wi = w_iter + it * (EE * 2) + 12 * r;   // 2 weights per edge, 6 edges
        g_wA[t] = make_float4(wi[0], wi[1], wi[2],  wi[3]);
        g_wB[t] = make_float4(wi[4], wi[5], wi[6],  wi[7]);
        g_wC[t] = make_float4(wi[8], wi[9], wi[10], wi[11]);
        const float* li = llr_iter + it * NN;
        const int* ev = edge_var + 6 * r;
        g_lwA[t] = make_float4(li[ev[0]] * LOG2E, li[ev[1]] * LOG2E,
                               li[ev[2]] * LOG2E, li[ev[3]] * LOG2E);
        g_lwB[t] = make_float2(li[ev[4]] * LOG2E, li[ev[5]] * LOG2E);
    }
    if (t < MM) {
        int e0 = 6 * t;
        unsigned pk[6];
#pragma unroll
        for (int j = 0; j < 6; j++)
            pk[j] = (unsigned)slot7(v_sum[2 * (e0 + j)]) |
                    ((unsigned)slot7(v_sum[2 * (e0 + j) + 1]) << 16);
        g_idxA[t] = make_uint4(pk[0], pk[1], pk[2], pk[3]);
        g_idxB[t] = make_uint2(pk[4], pk[5]);
        const int* ev = edge_var + e0;
        g_vsl[t] = make_uint4(
            (unsigned)lwslot(ev[0]) | ((unsigned)lwslot(ev[1]) << 16),
            (unsigned)lwslot(ev[2]) | ((unsigned)lwslot(ev[3]) << 16),
            (unsigned)lwslot(ev[4]) | ((unsigned)lwslot(ev[5]) << 16), 0u);
        g_finidx[t] = make_uint2((unsigned)slot7(fin_idx[3 * t]) |
                                 ((unsigned)slot7(fin_idx[3 * t + 1]) << 16),
                                 (unsigned)slot7(fin_idx[3 * t + 2]));
        g_finw[t] = make_float4(w_final[3 * t] * LN2, w_final[3 * t + 1] * LN2,
                                w_final[3 * t + 2] * LN2, llr_final[t]);
    }
}

// ------------------------------- fast math -----------------------------------
__device__ __forceinline__ float ex2f_(float x) { float y; asm("ex2.approx.f32 %0, %1;" : "=f"(y) : "f"(x)); return y; }
__device__ __forceinline__ float lg2f_(float x) { float y; asm("lg2.approx.f32 %0, %1;" : "=f"(y) : "f"(x)); return y; }
__device__ __forceinline__ float rcpf_(float x) { float y; asm("rcp.approx.f32 %0, %1;" : "=f"(y) : "f"(x)); return y; }

__device__ __forceinline__ float2 f2mul(float2 a, float2 b) { return make_float2(a.x * b.x, a.y * b.y); }
__device__ __forceinline__ float2 f2add1(float2 a) { return make_float2(a.x + 1.f, a.y + 1.f); }
__device__ __forceinline__ float2 f2sub1(float2 a) { return make_float2(a.x - 1.f, a.y - 1.f); }
// msg = lg2(B + c*A) - lg2(B - c*A)   (log2-domain c2v; ln2 folded into consumer weights)
__device__ __forceinline__ float2 lgpair(float2 B, float2 A) {
    float2 o;
    o.x = lg2f_(fmaf(CLIP, A.x, B.x)) - lg2f_(fmaf(-CLIP, A.x, B.x));
    o.y = lg2f_(fmaf(CLIP, A.y, B.y)) - lg2f_(fmaf(-CLIP, A.y, B.y));
    return o;
}

// Check node for one 2-lane pair: half-split extrinsic products of (E+1),(E-1).
// Writes the 6 extrinsic messages to dst[2*j] (stride-2 float2 within float4 slots).
__device__ __forceinline__ void check_pair(const float2* __restrict__ E,
                                           float2* __restrict__ dst) {
    float2 ep3 = f2add1(E[3]), em3 = f2sub1(E[3]);
    float2 ep4 = f2add1(E[4]), em4 = f2sub1(E[4]);
    float2 ep5 = f2add1(E[5]), em5 = f2sub1(E[5]);
    float2 p34 = f2mul(ep3, ep4), m34 = f2mul(em3, em4);
    float2 H2p = f2mul(p34, ep5), H2m = f2mul(m34, em5);

    float2 ep0 = f2add1(E[0]), em0 = f2sub1(E[0]);
    float2 ep1 = f2add1(E[1]), em1 = f2sub1(E[1]);
    float2 ep2 = f2add1(E[2]), em2 = f2sub1(E[2]);
    float2 p01 = f2mul(ep0, ep1), m01 = f2mul(em0, em1);
    float2 H1p = f2mul(p01, ep2), H1m = f2mul(m01, em2);

    dst[0]  = lgpair(f2mul(f2mul(ep1, ep2), H2p), f2mul(f2mul(em1, em2), H2m));
    dst[2]  = lgpair(f2mul(f2mul(ep0, ep2), H2p), f2mul(f2mul(em0, em2), H2m));
    dst[4]  = lgpair(f2mul(p01, H2p), f2mul(m01, H2m));
    dst[6]  = lgpair(f2mul(f2mul(ep4, ep5), H1p), f2mul(f2mul(em4, em5), H1m));
    dst[8]  = lgpair(f2mul(f2mul(ep3, ep5), H1p), f2mul(f2mul(em3, em5), H1m));
    dst[10] = lgpair(f2mul(p34, H1p), f2mul(m34, H1m));
}

// --------------------------------- main --------------------------------------
extern __shared__ float4 s_dyn[];

__global__ void __launch_bounds__(THREADS, 2)
bp_kernel(const float* __restrict__ llr, float* __restrict__ out) {
    float4* s_c2v = s_dyn;                 // CSLOTS float4 (56 KB), stride-7 padded
    float4* s_llr = s_dyn + CSLOTS;        // LW_SLOTS float4 (18 KB)
    const int tid = threadIdx.x;
    const long b0 = (long)blockIdx.x * WB;
    const float* llr0 = llr + b0 * NN;

    // stage raw llr (4 batch lanes per variable) - once
#pragma unroll
    for (int k = 0; k < NN / THREADS; k++) {
        int v = tid + k * THREADS;
        float4 L;
        L.x = llr0[v];
        L.y = llr0[NN + v];
        L.z = llr0[2 * NN + v];
        L.w = llr0[3 * NN + v];
        s_llr[lwslot(v)] = L;
    }
    // zero c2v (iteration 0 reads zeros)
#pragma unroll
    for (int k = 0; k < CSLOTS / THREADS; k++)
        s_c2v[tid + k * THREADS] = make_float4(0.f, 0.f, 0.f, 0.f);

    // iteration-invariant topology into registers
    uint4 iA = g_idxA[tid];
    uint2 iB = g_idxB[tid];
    uint4 vp = g_vsl[tid];
    unsigned idx[6] = { iA.x, iA.y, iA.z, iA.w, iB.x, iB.y };
    int vsl[6] = { (int)(vp.x & 0xFFFFu), (int)(vp.x >> 16),
                   (int)(vp.y & 0xFFFFu), (int)(vp.y >> 16),
                   (int)(vp.z & 0xFFFFu), (int)(vp.z >> 16) };
    __syncthreads();

    float2* dst = (float2*)s_c2v + tid * (2 * CSTRIDE);

    for (int it = 0; it < NITERS; it++) {
        int base = it * MM + tid;
        float4 wA = g_wA[base], wB = g_wB[base], wC = g_wC[base];
        float4 lA = g_lwA[base];
        float2 lB = g_lwB[base];
        float w0[6] = { wA.x, wA.z, wB.x, wB.z, wC.x, wC.z };
        float w1[6] = { wA.y, wA.w, wB.y, wB.w, wC.y, wC.w };
        float lw[6] = { lA.x, lA.y, lA.z, lA.w, lB.x, lB.y };

        float4 E4[6];
#pragma unroll
        for (int j = 0; j < 6; j++) {
            float4 A  = s_c2v[idx[j] & 0xFFFFu];
            float4 Bv = s_c2v[idx[j] >> 16];
            float4 L  = s_llr[vsl[j]];
            float ux = fminf(UCLAMP, fmaf(A.x, w0[j], fmaf(Bv.x, w1[j], L.x * lw[j])));
            float uy = fminf(UCLAMP, fmaf(A.y, w0[j], fmaf(Bv.y, w1[j], L.y * lw[j])));
            float uz = fminf(UCLAMP, fmaf(A.z, w0[j], fmaf(Bv.z, w1[j], L.z * lw[j])));
            float uw = fminf(UCLAMP, fmaf(A.w, w0[j], fmaf(Bv.w, w1[j], L.w * lw[j])));
            E4[j].x = ex2f_(ux);
            E4[j].y = ex2f_(uy);
            E4[j].z = ex2f_(uz);
            E4[j].w = ex2f_(uw);
        }
        __syncthreads();   // all reads of old c2v complete

        {
            float2 E[6];
#pragma unroll
            for (int j = 0; j < 6; j++) E[j] = make_float2(E4[j].x, E4[j].y);
            check_pair(E, dst);          // .xy halves
        }
        {
            float2 E[6];
#pragma unroll
            for (int j = 0; j < 6; j++) E[j] = make_float2(E4[j].z, E4[j].w);
            check_pair(E, dst + 1);      // .zw halves
        }
        __syncthreads();   // stores visible before next iteration's gathers
    }

    // final marginalization for variable v = tid (outputs are vars 0..511)
    uint2 fi = g_finidx[tid];
    float4 fw = g_finw[tid];
    float4 A  = s_c2v[fi.x & 0xFFFFu];
    float4 Bv = s_c2v[fi.x >> 16];
    float4 C  = s_c2v[fi.y];
    float4 L  = s_llr[lwslot(tid)];
    float4 o;
    o.x = fmaf(A.x, fw.x, fmaf(Bv.x, fw.y, fmaf(C.x, fw.z, L.x * fw.w)));
    o.y = fmaf(A.y, fw.x, fmaf(Bv.y, fw.y, fmaf(C.y, fw.z, L.y * fw.w)));
    o.z = fmaf(A.z, fw.x, fmaf(Bv.z, fw.y, fmaf(C.z, fw.z, L.z * fw.w)));
    o.w = fmaf(A.w, fw.x, fmaf(Bv.w, fw.y, fmaf(C.w, fw.z, L.w * fw.w)));
    out[(b0 + 0) * MM + tid] = rcpf_(1.0f + ex2f_(-o.x * LOG2E));
    out[(b0 + 1) * MM + tid] = rcpf_(1.0f + ex2f_(-o.y * LOG2E));
    out[(b0 + 2) * MM + tid] = rcpf_(1.0f + ex2f_(-o.z * LOG2E));
    out[(b0 + 3) * MM + tid] = rcpf_(1.0f + ex2f_(-o.w * LOG2E));
}

// ------------------------------ launch ---------------------------------------
extern "C" void kernel_launch(void* const* d_in, const int* in_sizes, int n_in,
                              void* d_out, int out_size) {
    const float* llr       = (const float*)d_in[0];
    const float* w_iter    = (const float*)d_in[1];
    const float* llr_iter  = (const float*)d_in[2];
    const float* w_final   = (const float*)d_in[3];
    const float* llr_final = (const float*)d_in[4];
    const int*   v_sum     = (const int*)d_in[5];
    // d_in[6] = c_prod_idx: redundant (check r owns edges 6r..6r+5 contiguously)
    const int*   edge_var  = (const int*)d_in[7];
    const int*   fin_idx   = (const int*)d_in[8];

    int B = in_sizes[0] / NN;                 // 8192
    size_t smem = (size_t)(CSLOTS + LW_SLOTS) * sizeof(float4);   // 74 KB

    cudaFuncSetAttribute(bp_kernel, cudaFuncAttributeMaxDynamicSharedMemorySize, (int)smem);

    prep_kernel<<<(NITERS * MM + 255) / 256, 256>>>(w_iter, llr_iter, w_final, llr_final,
                                                    v_sum, edge_var, fin_idx);
    bp_kernel<<<B / WB, THREADS, smem>>>(llr, (float*)d_out);
}